// round 7
// baseline (speedup 1.0000x reference)
#include <cuda_runtime.h>

// B=8, L=512, K=512, M=N=P=D=64
#define BB 8
#define LL 512
#define KS 512

typedef unsigned long long u64;

__device__ float g_vkc[BB * KS * 64];     // [b][k][n]
__device__ float g_S[BB * LL * KS];       // raw scaled scores [b][l][kc]

__device__ __forceinline__ void ffma2(u64& d, u64 a, u64 b) {
    asm("fma.rn.f32x2 %0, %1, %2, %0;" : "+l"(d) : "l"(a), "l"(b));
}
__device__ __forceinline__ void add2(u64& d, u64 a) {
    asm("add.rn.f32x2 %0, %0, %1;" : "+l"(d) : "l"(a));
}
__device__ __forceinline__ u64 pack2(float lo, float hi) {
    u64 r;
    asm("mov.b64 %0, {%1, %2};" : "=l"(r) : "f"(lo), "f"(hi));
    return r;
}
__device__ __forceinline__ void unpack2(u64 a, float& lo, float& hi) {
    asm("mov.b64 {%0, %1}, %2;" : "=f"(lo), "=f"(hi) : "l"(a));
}
__device__ __forceinline__ void cpa4(unsigned dst, const void* src) {
    asm volatile("cp.async.ca.shared.global [%0], [%1], 4;" :: "r"(dst), "l"(src));
}
__device__ __forceinline__ void cpa8(unsigned dst, const void* src) {
    asm volatile("cp.async.ca.shared.global [%0], [%1], 8;" :: "r"(dst), "l"(src));
}
__device__ __forceinline__ void cpa16(unsigned dst, const void* src) {
    asm volatile("cp.async.ca.shared.global [%0], [%1], 16;" :: "r"(dst), "l"(src));
}

// ---------------------------------------------------------------------------
// Kernel 1 (role-split, vkc FIRST so the leading waves saturate DRAM):
//   blocks [0,512):   vkc[b,k,n] = sum_p vk[b,k,p,n]*vexp[b,k,p]  (DRAM-bound)
//   blocks [512,768): scores  g_S[b][l][kc] = sc * q[l]·k[kc]     (FMA-bound)
// ---------------------------------------------------------------------------
#define SC_KST 0
#define SC_QT  8320
#define K1_SMEM_BYTES ((8320 + 64 * 33 * 2) * 4)   // 50176

__global__ __launch_bounds__(256)
void k1_kernel(const float* __restrict__ vk,
               const float* __restrict__ vexp,
               const float* __restrict__ q,
               const float* __restrict__ k,
               const float* __restrict__ scale_p) {
    extern __shared__ float sm[];
    const int tid = threadIdx.x;

    if (blockIdx.x < 512) {
        // ---------------- vkc role ----------------
        float* se = sm;                          // 512 floats
        const int vb  = blockIdx.x;              // 0..511
        const int bk0 = vb * 8;
        se[tid]       = vexp[(size_t)bk0 * 64 + tid];
        se[tid + 256] = vexp[(size_t)bk0 * 64 + tid + 256];
        __syncthreads();

        const int t  = vb * 256 + tid;           // 0 .. 131071
        const int n4 = t & 15;
        const int ph = (t >> 4) & 1;
        const int bk = t >> 5;
        const float4* vkp = (const float4*)(vk + (size_t)bk * 4096 + ph * 2048) + n4;
        const float* ve = se + (tid >> 5) * 64 + ph * 32;

        float4 acc = make_float4(0.f, 0.f, 0.f, 0.f);
#pragma unroll 8
        for (int p = 0; p < 32; ++p) {
            float4 v = vkp[p * 16];
            float e  = ve[p];
            acc.x = fmaf(v.x, e, acc.x);
            acc.y = fmaf(v.y, e, acc.y);
            acc.z = fmaf(v.z, e, acc.z);
            acc.w = fmaf(v.w, e, acc.w);
        }
        acc.x += __shfl_xor_sync(0xffffffffu, acc.x, 16);
        acc.y += __shfl_xor_sync(0xffffffffu, acc.y, 16);
        acc.z += __shfl_xor_sync(0xffffffffu, acc.z, 16);
        acc.w += __shfl_xor_sync(0xffffffffu, acc.w, 16);
        if (ph == 0)
            ((float4*)g_vkc)[(size_t)bk * 16 + n4] = acc;
        return;
    }

    // ---------------- scores role ----------------
    float* kst = sm + SC_KST;                    // [128 kc][65]
    u64*   qt2 = (u64*)(sm + SC_QT);             // [64 d][33]: l-pair packed q

    const int bid = blockIdx.x - 512;            // 0..255
    const int b   = bid >> 5;
    const int rem = bid & 31;
    const int l0  = (rem >> 2) * 64;
    const int kc0 = (rem & 3) * 128;
    const float* qb = q + ((size_t)b * LL + l0) * 64;
    const float* kb = k + ((size_t)b * KS + kc0) * 64;
    const float sc  = scale_p[0];

    {
        float* qw = (float*)qt2;
#pragma unroll
        for (int it = 0; it < 16; ++it) {
            int idx = it * 256 + tid;            // l*64 + d
            float v = qb[idx];
            int l = idx >> 6, d = idx & 63;
            qw[2 * (d * 33 + (l >> 1)) + (l & 1)] = v;
        }
    }
#pragma unroll
    for (int it = 0; it < 8; ++it) {
        int f4 = it * 256 + tid;                 // kc*16 + d4
        float4 v = ((const float4*)kb)[f4];
        int kc = f4 >> 4, d4 = (f4 & 15) * 4;
        float* dst = kst + kc * 65 + d4;
        dst[0] = v.x; dst[1] = v.y; dst[2] = v.z; dst[3] = v.w;
    }
    __syncthreads();

    const int lane = tid & 31;                   // kc = lane + 32*j
    const int lg   = tid >> 5;                   // l octet: 8*lg
    const float* kr = kst + lane * 65;

    u64 acc[4][4];
#pragma unroll
    for (int j = 0; j < 4; ++j)
#pragma unroll
        for (int p = 0; p < 4; ++p) acc[j][p] = 0ull;

#pragma unroll 4
    for (int d = 0; d < 64; ++d) {
        float k0 = kr[d];
        float k1 = kr[32 * 65 + d];
        float k2 = kr[64 * 65 + d];
        float k3 = kr[96 * 65 + d];
        u64 K0 = pack2(k0, k0), K1 = pack2(k1, k1);
        u64 K2 = pack2(k2, k2), K3 = pack2(k3, k3);
        const u64* qd = qt2 + d * 33 + 4 * lg;
        u64 q0 = qd[0], q1 = qd[1], q2 = qd[2], q3 = qd[3];
        ffma2(acc[0][0], K0, q0); ffma2(acc[0][1], K0, q1);
        ffma2(acc[0][2], K0, q2); ffma2(acc[0][3], K0, q3);
        ffma2(acc[1][0], K1, q0); ffma2(acc[1][1], K1, q1);
        ffma2(acc[1][2], K1, q2); ffma2(acc[1][3], K1, q3);
        ffma2(acc[2][0], K2, q0); ffma2(acc[2][1], K2, q1);
        ffma2(acc[2][2], K2, q2); ffma2(acc[2][3], K2, q3);
        ffma2(acc[3][0], K3, q0); ffma2(acc[3][1], K3, q1);
        ffma2(acc[3][2], K3, q2); ffma2(acc[3][3], K3, q3);
    }
#pragma unroll
    for (int p = 0; p < 4; ++p) {
        int l = l0 + 8 * lg + 2 * p;
        float* r0 = g_S + ((size_t)b * LL + l) * KS + kc0 + lane;
        float* r1 = r0 + KS;
#pragma unroll
        for (int j = 0; j < 4; ++j) {
            float lo, hi; unpack2(acc[j][p], lo, hi);
            r0[32 * j] = lo * sc;
            r1[32 * j] = hi * sc;
        }
    }
}

// ---------------------------------------------------------------------------
// Kernel 2 (fused softmax + tmp + vq-contraction + residual + LayerNorm):
//   per block: 32 l's, 512 threads. Pipeline over 16 n-chunks of 4:
//   cp.async streams vq (4-deep) + vkc (2-deep) while tmp_chunk computes.
// smem (words): W[32][512]=16384 | vq 4x[4][32][64]=32768 | vkc 2x[512][6]=6144
//               | tc[32][4]=128 | srow[32]
// ---------------------------------------------------------------------------
#define W_OFF  0
#define VQ_OFF 16384
#define VK_OFF 49152
#define TC_OFF 55296
#define SR_OFF 55424
#define K2_WORDS 55456
#define K2_SMEM_BYTES (K2_WORDS * 4)     // 221824

__device__ __forceinline__ void issue_k_chunk(unsigned smb, int b, int tid, int c) {
    if (c <= 15) {
        int kc = tid;                            // 512 rows, one per thread
        const float* src = g_vkc + ((size_t)b * KS + kc) * 64 + 4 * c;
        unsigned dst = smb + (VK_OFF + (c & 1) * 3072 + kc * 6) * 4;
        cpa8(dst, src);
        cpa8(dst + 8, src + 2);
    }
    asm volatile("cp.async.commit_group;");
}

__device__ __forceinline__ void issue_q_chunk(unsigned smb, const float* vq,
                                              int b, int l0, int tid, int c) {
    if (c <= 15) {
#pragma unroll
        for (int j = 0; j < 4; ++j) {
            int r = tid + 512 * j;               // l*64 + m
            int l = r >> 6, m = r & 63;
            const float* src = vq + (((size_t)(b * LL + l0 + l)) * 64 + m) * 64 + 4 * c;
            unsigned dw = VQ_OFF + (c & 3) * 8192 + l * 64 + m;
#pragma unroll
            for (int nn = 0; nn < 4; ++nn)
                cpa4(smb + (dw + nn * 2048) * 4, src + nn);
        }
    }
    asm volatile("cp.async.commit_group;");
}

__global__ __launch_bounds__(512, 1)
void k2_kernel(const float* __restrict__ q,
               const float* __restrict__ vq,
               const float* __restrict__ gamma,
               const float* __restrict__ beta,
               float* __restrict__ out) {
    extern __shared__ float sm[];
    float* W    = sm + W_OFF;                    // [32 l][512 kc]
    float* vkb  = sm + VK_OFF;
    float* tc   = sm + TC_OFF;                   // [32 l][4 n]
    float* srow = sm + SR_OFF;
    unsigned smb = (unsigned)__cvta_generic_to_shared(sm);

    const int tid  = threadIdx.x;
    const int w    = tid >> 5;
    const int lane = tid & 31;
    const int b    = blockIdx.x >> 4;
    const int l0   = (blockIdx.x & 15) << 5;

    // ---- prologue: issue S copy, vkc chunk0, vq chunks 0..2 (5 groups) ----
    {
        const float* gS = g_S + ((size_t)b * LL + l0) * KS;
#pragma unroll
        for (int j = 0; j < 8; ++j) {
            int idx = tid + 512 * j;             // float4 index, dst == W linear
            cpa16(smb + (W_OFF + idx * 4) * 4, gS + idx * 4);
        }
        asm volatile("cp.async.commit_group;");
    }
    issue_k_chunk(smb, b, tid, 0);
    issue_q_chunk(smb, vq, b, l0, tid, 0);
    issue_q_chunk(smb, vq, b, l0, tid, 1);
    issue_q_chunk(smb, vq, b, l0, tid, 2);

    // ---- wait S, softmax (overlaps chunk streaming) ----
    asm volatile("cp.async.wait_group 4;");
    __syncthreads();
#pragma unroll
    for (int r = 0; r < 2; ++r) {
        int l = w * 2 + r;
        float* Sr = W + l * 512;
        float m = -1e30f;
#pragma unroll
        for (int i = 0; i < 16; ++i) m = fmaxf(m, Sr[lane + 32 * i]);
#pragma unroll
        for (int o = 16; o > 0; o >>= 1)
            m = fmaxf(m, __shfl_xor_sync(0xffffffffu, m, o));
        float s = 0.f;
#pragma unroll
        for (int i = 0; i < 16; ++i) {
            float e = __expf(Sr[lane + 32 * i] - m);
            Sr[lane + 32 * i] = e;
            s += e;
        }
#pragma unroll
        for (int o = 16; o > 0; o >>= 1)
            s += __shfl_xor_sync(0xffffffffu, s, o);
        if (lane == 0) srow[l] = 1.f / s;
    }

    // attn accumulators: thread -> (l = tid>>4, m4 = (tid&15)*4)
    const int al  = tid >> 4;
    const int am4 = (tid & 15) * 4;
    u64 at0 = 0ull, at1 = 0ull;

    const float* Wl0 = W + (2 * w) * 512;
    const float* Wl1 = Wl0 + 512;

    // ---- main pipeline over 16 n-chunks ----
    for (int c = 0; c < 16; ++c) {
        if (c == 0) asm volatile("cp.async.wait_group 2;");
        else        asm volatile("cp.async.wait_group 1;");
        __syncthreads();

        issue_k_chunk(smb, b, tid, c + 1);
        issue_q_chunk(smb, vq, b, l0, tid, c + 3);

        // tmp_chunk: warp w -> l-pair (2w,2w+1); lane -> kc = lane+32j
        {
            const float* vkc = vkb + (c & 1) * 3072;
            u64 a00 = 0ull, a01 = 0ull, a10 = 0ull, a11 = 0ull;
#pragma unroll 4
            for (int j = 0; j < 16; ++j) {
                int kc = lane + 32 * j;
                float w0 = Wl0[kc], w1 = Wl1[kc];
                u64 W0 = pack2(w0, w0), W1 = pack2(w1, w1);
                u64 v01 = *(const u64*)(vkc + kc * 6);
                u64 v23 = *(const u64*)(vkc + kc * 6 + 2);
                ffma2(a00, W0, v01); ffma2(a01, W0, v23);
                ffma2(a10, W1, v01); ffma2(a11, W1, v23);
            }
#pragma unroll
            for (int off = 16; off > 0; off >>= 1) {
                add2(a00, __shfl_xor_sync(0xffffffffu, a00, off));
                add2(a01, __shfl_xor_sync(0xffffffffu, a01, off));
                add2(a10, __shfl_xor_sync(0xffffffffu, a10, off));
                add2(a11, __shfl_xor_sync(0xffffffffu, a11, off));
            }
            if (lane == 0) {
                float sr0 = srow[2 * w], sr1 = srow[2 * w + 1];
                float x, y;
                unpack2(a00, x, y); tc[(2 * w) * 4 + 0] = x * sr0; tc[(2 * w) * 4 + 1] = y * sr0;
                unpack2(a01, x, y); tc[(2 * w) * 4 + 2] = x * sr0; tc[(2 * w) * 4 + 3] = y * sr0;
                unpack2(a10, x, y); tc[(2 * w + 1) * 4 + 0] = x * sr1; tc[(2 * w + 1) * 4 + 1] = y * sr1;
                unpack2(a11, x, y); tc[(2 * w + 1) * 4 + 2] = x * sr1; tc[(2 * w + 1) * 4 + 3] = y * sr1;
            }
        }
        __syncthreads();

        // attn += vq_chunk · tmp_chunk
        {
            const float* vqc = sm + VQ_OFF + (c & 3) * 8192;
#pragma unroll
            for (int nn = 0; nn < 4; ++nn) {
                float tv = tc[al * 4 + nn];
                u64 T = pack2(tv, tv);
                float4 v = *(const float4*)(vqc + nn * 2048 + al * 64 + am4);
                ffma2(at0, T, pack2(v.x, v.y));
                ffma2(at1, T, pack2(v.z, v.w));
            }
        }
    }

    // ---- epilogue: residual + LayerNorm over 16-lane half-warp groups ----
    {
        float a0, a1, a2, a3;
        unpack2(at0, a0, a1);
        unpack2(at1, a2, a3);
        float4 qv = *(const float4*)(q + ((size_t)(b * LL + l0 + al)) * 64 + am4);
        float y0 = qv.x + a0, y1 = qv.y + a1, y2 = qv.z + a2, y3 = qv.w + a3;

        float s1 = y0 + y1 + y2 + y3;
#pragma unroll
        for (int o = 8; o > 0; o >>= 1)
            s1 += __shfl_xor_sync(0xffffffffu, s1, o);
        float mu = s1 * (1.f / 64.f);

        float d0 = y0 - mu, d1 = y1 - mu, d2 = y2 - mu, d3 = y3 - mu;
        float s2 = d0 * d0 + d1 * d1 + d2 * d2 + d3 * d3;
#pragma unroll
        for (int o = 8; o > 0; o >>= 1)
            s2 += __shfl_xor_sync(0xffffffffu, s2, o);
        float var = s2 * (1.f / 64.f);
        float r = rsqrtf(var + 1e-3f);

        float4 gm = *(const float4*)(gamma + am4);
        float4 bt = *(const float4*)(beta + am4);
        float4 o4;
        o4.x = d0 * r * gm.x + bt.x;
        o4.y = d1 * r * gm.y + bt.y;
        o4.z = d2 * r * gm.z + bt.z;
        o4.w = d3 * r * gm.w + bt.w;
        *(float4*)(out + ((size_t)(b * LL + l0 + al)) * 64 + am4) = o4;
    }
}

// ---------------------------------------------------------------------------
extern "C" void kernel_launch(void* const* d_in, const int* in_sizes, int n_in,
                              void* d_out, int out_size) {
    (void)in_sizes; (void)n_in; (void)out_size;
    const float* q     = (const float*)d_in[0];
    const float* k     = (const float*)d_in[1];
    const float* vq    = (const float*)d_in[2];
    const float* vk    = (const float*)d_in[3];
    const float* vexp  = (const float*)d_in[4];
    const float* scale = (const float*)d_in[5];
    const float* gamma = (const float*)d_in[6];
    const float* beta  = (const float*)d_in[7];
    float* out = (float*)d_out;

    cudaFuncSetAttribute(k1_kernel,
                         cudaFuncAttributeMaxDynamicSharedMemorySize,
                         K1_SMEM_BYTES);
    cudaFuncSetAttribute(k2_kernel,
                         cudaFuncAttributeMaxDynamicSharedMemorySize,
                         K2_SMEM_BYTES);

    k1_kernel<<<768, 256, K1_SMEM_BYTES>>>(vk, vexp, q, k, scale);
    k2_kernel<<<BB * (LL / 32), 512, K2_SMEM_BYTES>>>(q, vq, gamma, beta, out);
}

// round 9
// speedup vs baseline: 2.3180x; 2.3180x over previous
#include <cuda_runtime.h>

// B=8, L=512, K=512, M=N=P=D=64
#define BB 8
#define LL 512
#define KS 512

typedef unsigned long long u64;

__device__ float g_vkc[BB * KS * 64];     // [b][k][n]
__device__ float g_S[BB * LL * KS];       // raw scaled scores [b][l][kc]

__device__ __forceinline__ void ffma2(u64& d, u64 a, u64 b) {
    asm("fma.rn.f32x2 %0, %1, %2, %0;" : "+l"(d) : "l"(a), "l"(b));
}
__device__ __forceinline__ u64 pack2(float lo, float hi) {
    u64 r;
    asm("mov.b64 %0, {%1, %2};" : "=l"(r) : "f"(lo), "f"(hi));
    return r;
}
__device__ __forceinline__ void unpack2(u64 a, float& lo, float& hi) {
    asm("mov.b64 {%0, %1}, %2;" : "=f"(lo), "=f"(hi) : "l"(a));
}
__device__ __forceinline__ float hsum2(u64 a) {
    float lo, hi; unpack2(a, lo, hi);
    return lo + hi;
}

// ---------------------------------------------------------------------------
// Kernel 1 (role-split, vkc FIRST so the leading waves saturate DRAM):
//   blocks [0,512):   vkc[b,k,n] = sum_p vk[b,k,p,n]*vexp[b,k,p]  (DRAM-bound)
//   blocks [512,768): scores  g_S[b][l][kc] = sc * q[l]·k[kc]     (FMA-bound)
// ---------------------------------------------------------------------------
#define SC_KST 0
#define SC_QT  8320
#define K1_SMEM_BYTES ((8320 + 64 * 33 * 2) * 4)   // 50176

__global__ __launch_bounds__(256)
void k1_kernel(const float* __restrict__ vk,
               const float* __restrict__ vexp,
               const float* __restrict__ q,
               const float* __restrict__ k,
               const float* __restrict__ scale_p) {
    extern __shared__ float sm[];
    const int tid = threadIdx.x;

    if (blockIdx.x < 512) {
        // ---------------- vkc role ----------------
        float* se = sm;                          // 512 floats
        const int vb  = blockIdx.x;              // 0..511
        const int bk0 = vb * 8;
        se[tid]       = vexp[(size_t)bk0 * 64 + tid];
        se[tid + 256] = vexp[(size_t)bk0 * 64 + tid + 256];
        __syncthreads();

        const int t  = vb * 256 + tid;           // 0 .. 131071
        const int n4 = t & 15;
        const int ph = (t >> 4) & 1;
        const int bk = t >> 5;
        const float4* vkp = (const float4*)(vk + (size_t)bk * 4096 + ph * 2048) + n4;
        const float* ve = se + (tid >> 5) * 64 + ph * 32;

        float4 acc = make_float4(0.f, 0.f, 0.f, 0.f);
#pragma unroll 8
        for (int p = 0; p < 32; ++p) {
            float4 v = vkp[p * 16];
            float e  = ve[p];
            acc.x = fmaf(v.x, e, acc.x);
            acc.y = fmaf(v.y, e, acc.y);
            acc.z = fmaf(v.z, e, acc.z);
            acc.w = fmaf(v.w, e, acc.w);
        }
        acc.x += __shfl_xor_sync(0xffffffffu, acc.x, 16);
        acc.y += __shfl_xor_sync(0xffffffffu, acc.y, 16);
        acc.z += __shfl_xor_sync(0xffffffffu, acc.z, 16);
        acc.w += __shfl_xor_sync(0xffffffffu, acc.w, 16);
        if (ph == 0)
            ((float4*)g_vkc)[(size_t)bk * 16 + n4] = acc;
        return;
    }

    // ---------------- scores role ----------------
    float* kst = sm + SC_KST;                    // [128 kc][65]
    u64*   qt2 = (u64*)(sm + SC_QT);             // [64 d][33]: l-pair packed q

    const int bid = blockIdx.x - 512;            // 0..255
    const int b   = bid >> 5;
    const int rem = bid & 31;
    const int l0  = (rem >> 2) * 64;
    const int kc0 = (rem & 3) * 128;
    const float* qb = q + ((size_t)b * LL + l0) * 64;
    const float* kb = k + ((size_t)b * KS + kc0) * 64;
    const float sc  = scale_p[0];

    {
        float* qw = (float*)qt2;
#pragma unroll
        for (int it = 0; it < 16; ++it) {
            int idx = it * 256 + tid;            // l*64 + d
            float v = qb[idx];
            int l = idx >> 6, d = idx & 63;
            qw[2 * (d * 33 + (l >> 1)) + (l & 1)] = v;
        }
    }
#pragma unroll
    for (int it = 0; it < 8; ++it) {
        int f4 = it * 256 + tid;                 // kc*16 + d4
        float4 v = ((const float4*)kb)[f4];
        int kc = f4 >> 4, d4 = (f4 & 15) * 4;
        float* dst = kst + kc * 65 + d4;
        dst[0] = v.x; dst[1] = v.y; dst[2] = v.z; dst[3] = v.w;
    }
    __syncthreads();

    const int lane = tid & 31;                   // kc = lane + 32*j
    const int lg   = tid >> 5;                   // l octet: 8*lg
    const float* kr = kst + lane * 65;

    u64 acc[4][4];
#pragma unroll
    for (int j = 0; j < 4; ++j)
#pragma unroll
        for (int p = 0; p < 4; ++p) acc[j][p] = 0ull;

#pragma unroll 4
    for (int d = 0; d < 64; ++d) {
        float k0 = kr[d];
        float k1 = kr[32 * 65 + d];
        float k2 = kr[64 * 65 + d];
        float k3 = kr[96 * 65 + d];
        u64 K0 = pack2(k0, k0), K1 = pack2(k1, k1);
        u64 K2 = pack2(k2, k2), K3 = pack2(k3, k3);
        const u64* qd = qt2 + d * 33 + 4 * lg;
        u64 q0 = qd[0], q1 = qd[1], q2 = qd[2], q3 = qd[3];
        ffma2(acc[0][0], K0, q0); ffma2(acc[0][1], K0, q1);
        ffma2(acc[0][2], K0, q2); ffma2(acc[0][3], K0, q3);
        ffma2(acc[1][0], K1, q0); ffma2(acc[1][1], K1, q1);
        ffma2(acc[1][2], K1, q2); ffma2(acc[1][3], K1, q3);
        ffma2(acc[2][0], K2, q0); ffma2(acc[2][1], K2, q1);
        ffma2(acc[2][2], K2, q2); ffma2(acc[2][3], K2, q3);
        ffma2(acc[3][0], K3, q0); ffma2(acc[3][1], K3, q1);
        ffma2(acc[3][2], K3, q2); ffma2(acc[3][3], K3, q3);
    }
#pragma unroll
    for (int p = 0; p < 4; ++p) {
        int l = l0 + 8 * lg + 2 * p;
        float* r0 = g_S + ((size_t)b * LL + l) * KS + kc0 + lane;
        float* r1 = r0 + KS;
#pragma unroll
        for (int j = 0; j < 4; ++j) {
            float lo, hi; unpack2(acc[j][p], lo, hi);
            r0[32 * j] = lo * sc;
            r1[32 * j] = hi * sc;
        }
    }
}

// ---------------------------------------------------------------------------
// Kernel 2 (fused): per block 32 l's, 512 threads.
//   Phase 1: load S tile + vkc tile      (coalesced float4 LDG)
//   Phase 2: softmax (unnormalized, 1/sum stashed)
//   Phase 3: tmp[32][64] = W @ vkc       (R6 machinery, result -> smem)
//   Phase 4: attn[l][m] = vq[l][m][:]·tmp[l][:]  (full-row coalesced stream)
//   Phase 5: residual + LayerNorm -> out
// smem (words): W[32][512]=16384 | vkc[512][64]=32768 | tmp[32][64]=2048 | srow[32]
//   (W region reused for tmp-partials P[4][32][64], then for sy[32][64])
// ---------------------------------------------------------------------------
#define W_OFF  0
#define VK_OFF 16384
#define TMP_OFF 49152
#define SR_OFF  51200
#define K2_WORDS 51232
#define K2_SMEM_BYTES (K2_WORDS * 4)     // 204928

__global__ __launch_bounds__(512, 1)
void k2_kernel(const float* __restrict__ q,
               const float* __restrict__ vq,
               const float* __restrict__ gamma,
               const float* __restrict__ beta,
               float* __restrict__ out) {
    extern __shared__ float sm[];
    float* W    = sm + W_OFF;            // [32 l][512 kc]
    float* vkb  = sm + VK_OFF;           // [512 kc][64 n]
    float* stmp = sm + TMP_OFF;          // [32 l][64 n]
    float* srow = sm + SR_OFF;

    const int tid  = threadIdx.x;
    const int w    = tid >> 5;
    const int lane = tid & 31;
    const int b    = blockIdx.x >> 4;
    const int l0   = (blockIdx.x & 15) << 5;

    // ---- Phase 1: loads ----
    {
        const float4* gS4 = (const float4*)(g_S + ((size_t)b * LL + l0) * KS);
#pragma unroll
        for (int it = 0; it < 8; ++it)
            ((float4*)W)[it * 512 + tid] = gS4[it * 512 + tid];
        const float4* gv4 = (const float4*)(g_vkc + (size_t)b * KS * 64);
#pragma unroll 4
        for (int it = 0; it < 16; ++it)
            ((float4*)vkb)[it * 512 + tid] = gv4[it * 512 + tid];
    }
    __syncthreads();

    // ---- Phase 2: softmax on W rows ----
#pragma unroll
    for (int r = 0; r < 2; ++r) {
        int l = w * 2 + r;
        float* Sr = W + l * 512;
        float m = -1e30f;
#pragma unroll
        for (int i = 0; i < 16; ++i) m = fmaxf(m, Sr[lane + 32 * i]);
#pragma unroll
        for (int o = 16; o > 0; o >>= 1)
            m = fmaxf(m, __shfl_xor_sync(0xffffffffu, m, o));
        float s = 0.f;
#pragma unroll
        for (int i = 0; i < 16; ++i) {
            float e = __expf(Sr[lane + 32 * i] - m);
            Sr[lane + 32 * i] = e;
            s += e;
        }
#pragma unroll
        for (int o = 16; o > 0; o >>= 1)
            s += __shfl_xor_sync(0xffffffffu, s, o);
        if (lane == 0) srow[l] = 1.f / s;
    }
    __syncthreads();

    // ---- Phase 3: tmp = W @ vkc (4-way kc split, 8l x 2n tiles, FFMA2) ----
    const int kcs = w & 3;
    const int wq  = w >> 2;
    {
        u64 acc[8][2];
#pragma unroll
        for (int j = 0; j < 8; ++j) { acc[j][0] = 0ull; acc[j][1] = 0ull; }

        const float* vb = vkb + 2 * lane;
        const float* Wb = W + (8 * wq) * 512;
#pragma unroll 2
        for (int kk = 0; kk < 32; ++kk) {
            int kc = 128 * kcs + 4 * kk;
            const float* vr = vb + kc * 64;
            float2 va = *(const float2*)(vr);
            float2 vb2 = *(const float2*)(vr + 64);
            float2 vc = *(const float2*)(vr + 128);
            float2 vd = *(const float2*)(vr + 192);
            u64 A0 = pack2(va.x, vb2.x), A1 = pack2(va.y, vb2.y);
            u64 B0 = pack2(vc.x, vd.x),  B1 = pack2(vc.y, vd.y);
#pragma unroll
            for (int j = 0; j < 8; ++j) {
                float4 wv = *(const float4*)(Wb + j * 512 + kc);  // aligned bcast
                u64 w01 = pack2(wv.x, wv.y);
                u64 w23 = pack2(wv.z, wv.w);
                ffma2(acc[j][0], w01, A0); ffma2(acc[j][1], w01, A1);
                ffma2(acc[j][0], w23, B0); ffma2(acc[j][1], w23, B1);
            }
        }
        __syncthreads();                 // W reads done; reuse W region for P

        float* P = W + kcs * 2048;       // P[kcs][32 l][64 n]
#pragma unroll
        for (int j = 0; j < 8; ++j) {
            int l = 8 * wq + j;
            *(float2*)(P + l * 64 + 2 * lane) =
                make_float2(hsum2(acc[j][0]), hsum2(acc[j][1]));
        }
    }
    __syncthreads();

    // reduce 4 partials -> stmp (normalized)
    {
        int idx = tid * 4;               // l = idx>>6
        int l   = idx >> 6;
        float4 s0 = *(const float4*)(W + idx);
        float4 s1 = *(const float4*)(W + 2048 + idx);
        float4 s2 = *(const float4*)(W + 4096 + idx);
        float4 s3 = *(const float4*)(W + 6144 + idx);
        float inv = srow[l];
        float4 o;
        o.x = (s0.x + s1.x + s2.x + s3.x) * inv;
        o.y = (s0.y + s1.y + s2.y + s3.y) * inv;
        o.z = (s0.z + s1.z + s2.z + s3.z) * inv;
        o.w = (s0.w + s1.w + s2.w + s3.w) * inv;
        *(float4*)(stmp + idx) = o;
    }
    __syncthreads();

    // ---- Phase 4: attn rows — full-row coalesced vq stream ----
    // row r = it*512 + tid: l = r>>6, m = r&63; vq row is 64 contiguous floats.
    float* sy = W;                       // [32 l][64 m], W region dead
    const float* vqb = vq + ((size_t)(b * LL + l0)) * 4096;
    const float* qb  = q + ((size_t)(b * LL + l0)) * 64;
#pragma unroll
    for (int it = 0; it < 4; ++it) {
        int r = it * 512 + tid;
        int l = r >> 6, m = r & 63;
        const float4* row = (const float4*)(vqb + (size_t)r * 64);
        const float*  tp  = stmp + l * 64;
        float a0 = 0.f, a1 = 0.f, a2 = 0.f, a3 = 0.f;
#pragma unroll
        for (int i = 0; i < 4; ++i) {
            float4 v0 = row[4 * i + 0];
            float4 v1 = row[4 * i + 1];
            float4 v2 = row[4 * i + 2];
            float4 v3 = row[4 * i + 3];
            const float* t0 = tp + 16 * i;
            a0 = fmaf(v0.x, t0[0],  fmaf(v0.y, t0[1],
                 fmaf(v0.z, t0[2],  fmaf(v0.w, t0[3],  a0))));
            a1 = fmaf(v1.x, t0[4],  fmaf(v1.y, t0[5],
                 fmaf(v1.z, t0[6],  fmaf(v1.w, t0[7],  a1))));
            a2 = fmaf(v2.x, t0[8],  fmaf(v2.y, t0[9],
                 fmaf(v2.z, t0[10], fmaf(v2.w, t0[11], a2))));
            a3 = fmaf(v3.x, t0[12], fmaf(v3.y, t0[13],
                 fmaf(v3.z, t0[14], fmaf(v3.w, t0[15], a3))));
        }
        sy[r] = qb[r] + ((a0 + a1) + (a2 + a3));
    }
    __syncthreads();

    // ---- Phase 5: LayerNorm per l (16 warps x 2 rows) ----
#pragma unroll
    for (int r = 0; r < 2; ++r) {
        int l = w * 2 + r;
        const float* yr = sy + l * 64;
        float y0 = yr[lane], y1 = yr[lane + 32];
        float s1 = y0 + y1;
#pragma unroll
        for (int o = 16; o > 0; o >>= 1)
            s1 += __shfl_xor_sync(0xffffffffu, s1, o);
        float mu = s1 * (1.f / 64.f);
        float d0 = y0 - mu, d1 = y1 - mu;
        float s2 = d0 * d0 + d1 * d1;
#pragma unroll
        for (int o = 16; o > 0; o >>= 1)
            s2 += __shfl_xor_sync(0xffffffffu, s2, o);
        float var = s2 * (1.f / 64.f);
        float rs = rsqrtf(var + 1e-3f);
        float* op = out + ((size_t)(b * LL + l0 + l)) * 64;
        op[lane]      = d0 * rs * __ldg(gamma + lane)      + __ldg(beta + lane);
        op[lane + 32] = d1 * rs * __ldg(gamma + lane + 32) + __ldg(beta + lane + 32);
    }
}

// ---------------------------------------------------------------------------
extern "C" void kernel_launch(void* const* d_in, const int* in_sizes, int n_in,
                              void* d_out, int out_size) {
    (void)in_sizes; (void)n_in; (void)out_size;
    const float* q     = (const float*)d_in[0];
    const float* k     = (const float*)d_in[1];
    const float* vq    = (const float*)d_in[2];
    const float* vk    = (const float*)d_in[3];
    const float* vexp  = (const float*)d_in[4];
    const float* scale = (const float*)d_in[5];
    const float* gamma = (const float*)d_in[6];
    const float* beta  = (const float*)d_in[7];
    float* out = (float*)d_out;

    cudaFuncSetAttribute(k1_kernel,
                         cudaFuncAttributeMaxDynamicSharedMemorySize,
                         K1_SMEM_BYTES);
    cudaFuncSetAttribute(k2_kernel,
                         cudaFuncAttributeMaxDynamicSharedMemorySize,
                         K2_SMEM_BYTES);

    k1_kernel<<<768, 256, K1_SMEM_BYTES>>>(vk, vexp, q, k, scale);
    k2_kernel<<<BB * (LL / 32), 512, K2_SMEM_BYTES>>>(q, vq, gamma, beta, out);
}

// round 13
// speedup vs baseline: 3.3328x; 1.4378x over previous
#include <cuda_runtime.h>

// B=8, L=512, K=512, M=N=P=D=64
#define BB 8
#define LL 512
#define KS 512

typedef unsigned long long u64;

__device__ float g_vkc[BB * KS * 64];     // [b][k][n]
__device__ float g_tmp[BB * LL * 64];     // [b][l][n]

__device__ __forceinline__ void ffma2(u64& d, u64 a, u64 b) {
    asm("fma.rn.f32x2 %0, %1, %2, %0;" : "+l"(d) : "l"(a), "l"(b));
}
__device__ __forceinline__ u64 pack2(float lo, float hi) {
    u64 r;
    asm("mov.b64 %0, {%1, %2};" : "=l"(r) : "f"(lo), "f"(hi));
    return r;
}
__device__ __forceinline__ void unpack2(u64 a, float& lo, float& hi) {
    asm("mov.b64 {%0, %1}, %2;" : "=f"(lo), "=f"(hi) : "l"(a));
}
__device__ __forceinline__ float hsum2(u64 a) {
    float lo, hi; unpack2(a, lo, hi);
    return lo + hi;
}

// ---------------------------------------------------------------------------
// Kernel 1: vkc[b,k,n] = sum_p vk[b,k,p,n]*vexp[b,k,p]   (streams vk, 67MB)
//   4-way p-split: 262144 threads, each sums 16 p's (16x LDG.128 in flight).
//   Combine: shfl (ph low bit) + smem (ph high bit).
// ---------------------------------------------------------------------------
__global__ __launch_bounds__(256)
void vkc_kernel(const float* __restrict__ vk,
                const float* __restrict__ vexp) {
    __shared__ float  se[256];                   // vexp for 4 bk's
    __shared__ float4 sred[64];                  // cross-warp partials [lb][n4]

    const int tid = threadIdx.x;
    const int bk0 = blockIdx.x * 4;
    se[tid] = vexp[(size_t)bk0 * 64 + tid];
    __syncthreads();

    const int n4 = tid & 15;
    const int ph = (tid >> 4) & 3;               // p quarter
    const int lb = tid >> 6;                     // local bk 0..3
    const int bk = bk0 + lb;

    const float4* vkp = (const float4*)(vk + (size_t)bk * 4096) + ph * 256 + n4;
    const float* ve = se + lb * 64 + ph * 16;

    float4 acc = make_float4(0.f, 0.f, 0.f, 0.f);
#pragma unroll
    for (int p = 0; p < 16; ++p) {
        float4 v = vkp[p * 16];
        float e  = ve[p];
        acc.x = fmaf(v.x, e, acc.x);
        acc.y = fmaf(v.y, e, acc.y);
        acc.z = fmaf(v.z, e, acc.z);
        acc.w = fmaf(v.w, e, acc.w);
    }
    // combine ph low-bit within warp (lane bit 4)
    acc.x += __shfl_xor_sync(0xffffffffu, acc.x, 16);
    acc.y += __shfl_xor_sync(0xffffffffu, acc.y, 16);
    acc.z += __shfl_xor_sync(0xffffffffu, acc.z, 16);
    acc.w += __shfl_xor_sync(0xffffffffu, acc.w, 16);

    const int lane = tid & 31;
    const int ph_hi = (tid >> 5) & 1;            // warp parity = ph high bit
    if (ph_hi == 1 && lane < 16)
        sred[lb * 16 + n4] = acc;
    __syncthreads();
    if (ph_hi == 0 && lane < 16) {
        float4 o = sred[lb * 16 + n4];
        o.x += acc.x; o.y += acc.y; o.z += acc.z; o.w += acc.w;
        ((float4*)g_vkc)[(size_t)bk * 16 + n4] = o;
    }
}

// ---------------------------------------------------------------------------
// Kernel 2: per block (b, 32 l's), 512 threads:
//   stage k (L2-shared across 16 blocks/b) -> scores -> softmax ->
//   stage vkc -> tmp = W @ vkc -> g_tmp
// smem (words): kst[512*65]=33280 (k, later vkc 512*64) | W[32*512]=16384
//               | qt2[64*17 u64]=2176 | srow[32]
// ---------------------------------------------------------------------------
#define KST_W 0
#define W_OFF 33280
#define QT_OFF 49664
#define SR_OFF (QT_OFF + 2176)                   // 51840
#define K2_WORDS (SR_OFF + 32)                   // 51872
#define K2_SMEM_BYTES (K2_WORDS * 4)             // 207488

__global__ __launch_bounds__(512, 1)
void k2_kernel(const float* __restrict__ q,
               const float* __restrict__ k,
               const float* __restrict__ scale_p) {
    extern __shared__ float sm[];
    float* kst  = sm + KST_W;                    // k [512 kc][65] / vkc [512][64]
    float* W    = sm + W_OFF;                    // [32 l][512 kc]
    u64*   qt2  = (u64*)(sm + QT_OFF);           // [64 d][17]: l-pair packed q
    float* srow = sm + SR_OFF;

    const int tid  = threadIdx.x;
    const int w    = tid >> 5;
    const int lane = tid & 31;
    const int b    = blockIdx.x >> 4;
    const int l0   = (blockIdx.x & 15) << 5;
    const float* qb = q + ((size_t)b * LL + l0) * 64;
    const float* kb = k + (size_t)b * KS * 64;
    const float sc  = scale_p[0];

    // ---- stage q as l-pairs: qt2[d*17 + lp] = (q[2lp][d], q[2lp+1][d]) ----
#pragma unroll
    for (int it = 0; it < 2; ++it) {
        int f  = it * 512 + tid;                 // 0..1023
        int lp = f >> 6, d = f & 63;
        qt2[d * 17 + lp] = pack2(qb[(2 * lp) * 64 + d], qb[(2 * lp + 1) * 64 + d]);
    }
    // ---- stage k [512 kc][64 d] at pitch 65 ----
#pragma unroll 4
    for (int it = 0; it < 16; ++it) {
        int f4 = it * 512 + tid;                 // kc*16 + d4
        float4 v = ((const float4*)kb)[f4];
        int kc = f4 >> 4, d4 = (f4 & 15) * 4;
        float* dst = kst + kc * 65 + d4;
        dst[0] = v.x; dst[1] = v.y; dst[2] = v.z; dst[3] = v.w;
    }
    __syncthreads();

    // ---- scores: thread tile 4kc x 8l, FFMA2 over l-pairs ----
    {
        const int lg  = tid & 3;                 // l octet
        const int kcg = tid >> 2;                // 0..127 -> 4 kc at 4*kcg
        const float* kr = kst + 4 * kcg * 65;

        u64 acc[4][4];
#pragma unroll
        for (int j = 0; j < 4; ++j)
#pragma unroll
            for (int p = 0; p < 4; ++p) acc[j][p] = 0ull;

#pragma unroll 4
        for (int d = 0; d < 64; ++d) {
            float k0 = kr[d];
            float k1 = kr[65 + d];
            float k2 = kr[130 + d];
            float k3 = kr[195 + d];
            u64 K0 = pack2(k0, k0), K1 = pack2(k1, k1);
            u64 K2 = pack2(k2, k2), K3 = pack2(k3, k3);
            const u64* qd = qt2 + d * 17 + 4 * lg;
            u64 q0 = qd[0], q1 = qd[1], q2 = qd[2], q3 = qd[3];
            ffma2(acc[0][0], K0, q0); ffma2(acc[0][1], K0, q1);
            ffma2(acc[0][2], K0, q2); ffma2(acc[0][3], K0, q3);
            ffma2(acc[1][0], K1, q0); ffma2(acc[1][1], K1, q1);
            ffma2(acc[1][2], K1, q2); ffma2(acc[1][3], K1, q3);
            ffma2(acc[2][0], K2, q0); ffma2(acc[2][1], K2, q1);
            ffma2(acc[2][2], K2, q2); ffma2(acc[2][3], K2, q3);
            ffma2(acc[3][0], K3, q0); ffma2(acc[3][1], K3, q1);
            ffma2(acc[3][2], K3, q2); ffma2(acc[3][3], K3, q3);
        }
        // store scaled scores into W[l][kc]
#pragma unroll
        for (int j = 0; j < 4; ++j)
#pragma unroll
            for (int p = 0; p < 4; ++p) {
                float lo, hi; unpack2(acc[j][p], lo, hi);
                int l  = 8 * lg + 2 * p;
                int kc = 4 * kcg + j;
                W[l * 512 + kc]       = lo * sc;
                W[(l + 1) * 512 + kc] = hi * sc;
            }
    }
    __syncthreads();

    // ---- softmax on W rows (unnormalized; 1/sum stashed) ----
#pragma unroll
    for (int r = 0; r < 2; ++r) {
        int l = w * 2 + r;
        float* Sr = W + l * 512;
        float m = -1e30f;
#pragma unroll
        for (int i = 0; i < 16; ++i) m = fmaxf(m, Sr[lane + 32 * i]);
#pragma unroll
        for (int o = 16; o > 0; o >>= 1)
            m = fmaxf(m, __shfl_xor_sync(0xffffffffu, m, o));
        float s = 0.f;
#pragma unroll
        for (int i = 0; i < 16; ++i) {
            float e = __expf(Sr[lane + 32 * i] - m);
            Sr[lane + 32 * i] = e;
            s += e;
        }
#pragma unroll
        for (int o = 16; o > 0; o >>= 1)
            s += __shfl_xor_sync(0xffffffffu, s, o);
        if (lane == 0) srow[l] = 1.f / s;
    }
    __syncthreads();

    // ---- stage vkc into kst region: [512 kc][64 n] (overwrites k) ----
    {
        const float4* gv4 = (const float4*)(g_vkc + (size_t)b * KS * 64);
#pragma unroll 4
        for (int it = 0; it < 16; ++it)
            ((float4*)kst)[it * 512 + tid] = gv4[it * 512 + tid];
    }
    __syncthreads();

    // ---- tmp: 4-way kc split, tile 8l x 2n, FFMA2 over kc-pairs ----
    const int kcs = w & 3;
    const int wq  = w >> 2;
    {
        u64 acc[8][2];
#pragma unroll
        for (int j = 0; j < 8; ++j) { acc[j][0] = 0ull; acc[j][1] = 0ull; }

        const float* vb = kst + 2 * lane;
        const float* Wb = W + (8 * wq) * 512;
#pragma unroll 2
        for (int kk = 0; kk < 32; ++kk) {
            int kc = 128 * kcs + 4 * kk;
            const float* vr = vb + kc * 64;
            float2 va = *(const float2*)(vr);
            float2 vb2 = *(const float2*)(vr + 64);
            float2 vc = *(const float2*)(vr + 128);
            float2 vd = *(const float2*)(vr + 192);
            u64 A0 = pack2(va.x, vb2.x), A1 = pack2(va.y, vb2.y);
            u64 B0 = pack2(vc.x, vd.x),  B1 = pack2(vc.y, vd.y);
#pragma unroll
            for (int j = 0; j < 8; ++j) {
                float4 wv = *(const float4*)(Wb + j * 512 + kc);  // bcast
                u64 w01 = pack2(wv.x, wv.y);
                u64 w23 = pack2(wv.z, wv.w);
                ffma2(acc[j][0], w01, A0); ffma2(acc[j][1], w01, A1);
                ffma2(acc[j][0], w23, B0); ffma2(acc[j][1], w23, B1);
            }
        }
        __syncthreads();                         // W reads done; reuse for P

        float* P = W + kcs * 2048;               // P[kcs][32 l][64 n]
#pragma unroll
        for (int j = 0; j < 8; ++j) {
            int l = 8 * wq + j;
            *(float2*)(P + l * 64 + 2 * lane) =
                make_float2(hsum2(acc[j][0]), hsum2(acc[j][1]));
        }
    }
    __syncthreads();

    // ---- reduce partials, normalize, write g_tmp ----
    {
        int idx = tid * 4;                       // l = idx>>6
        int l   = idx >> 6;
        float4 s0 = *(const float4*)(W + idx);
        float4 s1 = *(const float4*)(W + 2048 + idx);
        float4 s2 = *(const float4*)(W + 4096 + idx);
        float4 s3 = *(const float4*)(W + 6144 + idx);
        float inv = srow[l];
        float4 o;
        o.x = (s0.x + s1.x + s2.x + s3.x) * inv;
        o.y = (s0.y + s1.y + s2.y + s3.y) * inv;
        o.z = (s0.z + s1.z + s2.z + s3.z) * inv;
        o.w = (s0.w + s1.w + s2.w + s3.w) * inv;
        *(float4*)(g_tmp + ((size_t)b * LL + l0) * 64 + idx) = o;
    }
}

// ---------------------------------------------------------------------------
// Kernel 3: per (b,l): attn = vq @ tmp; out = LayerNorm(q + attn)  (streams vq)
// ---------------------------------------------------------------------------
__global__ __launch_bounds__(256)
void out_kernel(const float* __restrict__ q,
                const float* __restrict__ vq,
                const float* __restrict__ gamma,
                const float* __restrict__ beta,
                float* __restrict__ out) {
    __shared__ float stmp[64];
    __shared__ float sq[64];
    __shared__ float sy[64];
    __shared__ float red[4];

    const int tid = threadIdx.x;
    const int bl  = blockIdx.x;
    if (tid < 64) {
        stmp[tid] = g_tmp[(size_t)bl * 64 + tid];
        sq[tid]   = q[(size_t)bl * 64 + tid];
    }
    __syncthreads();

    const int m    = tid >> 2;
    const int part = tid & 3;
    const float4* vr = (const float4*)(vq + (size_t)bl * 4096 + m * 64) + part * 4;
    float acc = 0.f;
#pragma unroll
    for (int i = 0; i < 4; ++i) {
        float4 v = vr[i];
        const float* tp = stmp + part * 16 + i * 4;
        acc = fmaf(v.x, tp[0],
              fmaf(v.y, tp[1],
              fmaf(v.z, tp[2],
              fmaf(v.w, tp[3], acc))));
    }
    acc += __shfl_xor_sync(0xffffffffu, acc, 1);
    acc += __shfl_xor_sync(0xffffffffu, acc, 2);
    if (part == 0) sy[m] = sq[m] + acc;
    __syncthreads();

    float y = 0.f;
    if (tid < 64) {
        y = sy[tid];
        float s1 = y;
#pragma unroll
        for (int o = 16; o > 0; o >>= 1)
            s1 += __shfl_xor_sync(0xffffffffu, s1, o);
        if ((tid & 31) == 0) red[tid >> 5] = s1;
    }
    __syncthreads();
    float mu = (red[0] + red[1]) * (1.f / 64.f);
    if (tid < 64) {
        float d = y - mu;
        float s2 = d * d;
#pragma unroll
        for (int o = 16; o > 0; o >>= 1)
            s2 += __shfl_xor_sync(0xffffffffu, s2, o);
        if ((tid & 31) == 0) red[2 + (tid >> 5)] = s2;
    }
    __syncthreads();
    if (tid < 64) {
        float var = (red[2] + red[3]) * (1.f / 64.f);
        float r = rsqrtf(var + 1e-3f);
        out[(size_t)bl * 64 + tid] =
            (y - mu) * r * __ldg(gamma + tid) + __ldg(beta + tid);
    }
}

// ---------------------------------------------------------------------------
extern "C" void kernel_launch(void* const* d_in, const int* in_sizes, int n_in,
                              void* d_out, int out_size) {
    (void)in_sizes; (void)n_in; (void)out_size;
    const float* q     = (const float*)d_in[0];
    const float* k     = (const float*)d_in[1];
    const float* vq    = (const float*)d_in[2];
    const float* vk    = (const float*)d_in[3];
    const float* vexp  = (const float*)d_in[4];
    const float* scale = (const float*)d_in[5];
    const float* gamma = (const float*)d_in[6];
    const float* beta  = (const float*)d_in[7];
    float* out = (float*)d_out;

    cudaFuncSetAttribute(k2_kernel,
                         cudaFuncAttributeMaxDynamicSharedMemorySize,
                         K2_SMEM_BYTES);

    vkc_kernel<<<BB * KS / 4, 256>>>(vk, vexp);
    k2_kernel<<<BB * (LL / 32), 512, K2_SMEM_BYTES>>>(q, k, scale);
    out_kernel<<<BB * LL, 256>>>(q, vq, gamma, beta, out);
}